// round 8
// baseline (speedup 1.0000x reference)
#include <cuda_runtime.h>
#include <cuda_bf16.h>
#include <cstdint>

// Problem constants (fixed shapes)
#define NN      50000
#define EE      800000
#define IN_C    64
#define EDGE_C  32
#define OUT_C   64
#define TILE_E  64
#define N_TILES (EE / TILE_E)   // 12500 exactly
#define CS_STRIDE 68            // padded C_s row stride (floats)

// Scratch (device globals; 16B-aligned for v4 access)
__device__ __align__(16) float g_A[NN * OUT_C];   // x @ W1[0:64]
__device__ __align__(16) float g_B[NN * OUT_C];   // x @ W1[64:128]
__device__ __align__(16) float g_H[NN * OUT_C];   // scatter-sum of relu(h)
__device__ int g_deg[NN];                          // in-degree

typedef unsigned long long u64;

// ---------------------------------------------------------------------------
// helpers
// ---------------------------------------------------------------------------
__device__ __forceinline__ u64 dup2(float v) {
    u64 r; asm("mov.b64 %0, {%1, %1};" : "=l"(r) : "f"(v)); return r;
}
__device__ __forceinline__ void fma2(u64& d, u64 a, u64 b) {
    asm("fma.rn.f32x2 %0, %1, %2, %0;" : "+l"(d) : "l"(a), "l"(b));
}
__device__ __forceinline__ float2 unpack2(u64 v) {
    float2 f; asm("mov.b64 {%0, %1}, %2;" : "=f"(f.x), "=f"(f.y) : "l"(v)); return f;
}
__device__ __forceinline__ void red_add_v4(float* p, float4 v) {
    asm volatile("red.global.add.v4.f32 [%0], {%1, %2, %3, %4};"
                 :: "l"(p), "f"(v.x), "f"(v.y), "f"(v.z), "f"(v.w)
                 : "memory");
}
__device__ __forceinline__ uint32_t f2tf32(float f) {
    uint32_t r; asm("cvt.rna.tf32.f32 %0, %1;" : "=r"(r) : "f"(f)); return r;
}
__device__ __forceinline__ void mma_tf32(float& c0, float& c1, float& c2, float& c3,
                                         uint32_t a0, uint32_t a1, uint32_t a2, uint32_t a3,
                                         uint32_t b0, uint32_t b1) {
    asm volatile(
        "mma.sync.aligned.m16n8k8.row.col.f32.tf32.tf32.f32 "
        "{%0,%1,%2,%3},{%4,%5,%6,%7},{%8,%9},{%0,%1,%2,%3};"
        : "+f"(c0), "+f"(c1), "+f"(c2), "+f"(c3)
        : "r"(a0), "r"(a1), "r"(a2), "r"(a3), "r"(b0), "r"(b1));
}

// ---------------------------------------------------------------------------
// Kernel 0: zero H accumulator + degrees
// ---------------------------------------------------------------------------
__global__ void zero_kernel() {
    int id = blockIdx.x * blockDim.x + threadIdx.x;
    if (id < (NN * OUT_C) / 4) {
        reinterpret_cast<float4*>(g_H)[id] = make_float4(0.f, 0.f, 0.f, 0.f);
    }
    if (id < NN) g_deg[id] = 0;
}

// ---------------------------------------------------------------------------
// Kernel 0b: degree histogram
// ---------------------------------------------------------------------------
__global__ void hist_kernel(const int* __restrict__ col) {
    int e = blockIdx.x * blockDim.x + threadIdx.x;
    if (e < EE) atomicAdd(&g_deg[col[e]], 1);
}

// ---------------------------------------------------------------------------
// Kernel 1: per-node precompute  A = x @ W1a,  B = x @ W1b  (fp32)
// ---------------------------------------------------------------------------
__global__ __launch_bounds__(256)
void pre_kernel(const float* __restrict__ x, const float* __restrict__ W1) {
    __shared__ __align__(16) float Wa_s[IN_C * OUT_C];
    __shared__ __align__(16) float Wb_s[IN_C * OUT_C];
    __shared__ __align__(16) float x_s[64 * IN_C];

    int t = threadIdx.x;
    for (int i = t; i < IN_C * OUT_C; i += 256) {
        Wa_s[i] = W1[i];
        Wb_s[i] = W1[IN_C * OUT_C + i];
    }

    const int tc = t & 15;
    const int tn = t >> 4;
    const int base = blockIdx.x * 64;
    {
        const float4* x4 = reinterpret_cast<const float4*>(x);
        float4* xs4 = reinterpret_cast<float4*>(x_s);
        #pragma unroll
        for (int i = 0; i < 4; i++) {
            int id = t + 256 * i;
            int n = id >> 4, q = id & 15;
            int gn = base + n;
            float4 v = make_float4(0.f, 0.f, 0.f, 0.f);
            if (gn < NN) v = x4[gn * 16 + q];
            xs4[n * 16 + q] = v;
        }
    }
    __syncthreads();

    u64 aAL[4], aAH[4], aBL[4], aBH[4];
    #pragma unroll
    for (int n = 0; n < 4; n++) { aAL[n] = 0; aAH[n] = 0; aBL[n] = 0; aBH[n] = 0; }

    const ulonglong2* wa2 = reinterpret_cast<const ulonglong2*>(Wa_s);
    const ulonglong2* wb2 = reinterpret_cast<const ulonglong2*>(Wb_s);
    const float4* xs4 = reinterpret_cast<const float4*>(x_s);

    #pragma unroll
    for (int kb = 0; kb < IN_C / 4; kb++) {
        ulonglong2 wa[4], wb[4];
        #pragma unroll
        for (int kk = 0; kk < 4; kk++) {
            wa[kk] = wa2[(4 * kb + kk) * 16 + tc];
            wb[kk] = wb2[(4 * kb + kk) * 16 + tc];
        }
        #pragma unroll
        for (int n = 0; n < 4; n++) {
            float4 v4 = xs4[(4 * tn + n) * 16 + kb];
            u64 d0 = dup2(v4.x), d1 = dup2(v4.y), d2 = dup2(v4.z), d3 = dup2(v4.w);
            fma2(aAL[n], d0, wa[0].x); fma2(aAH[n], d0, wa[0].y);
            fma2(aBL[n], d0, wb[0].x); fma2(aBH[n], d0, wb[0].y);
            fma2(aAL[n], d1, wa[1].x); fma2(aAH[n], d1, wa[1].y);
            fma2(aBL[n], d1, wb[1].x); fma2(aBH[n], d1, wb[1].y);
            fma2(aAL[n], d2, wa[2].x); fma2(aAH[n], d2, wa[2].y);
            fma2(aBL[n], d2, wb[2].x); fma2(aBH[n], d2, wb[2].y);
            fma2(aAL[n], d3, wa[3].x); fma2(aAH[n], d3, wa[3].y);
            fma2(aBL[n], d3, wb[3].x); fma2(aBH[n], d3, wb[3].y);
        }
    }

    float4* A4 = reinterpret_cast<float4*>(g_A);
    float4* B4 = reinterpret_cast<float4*>(g_B);
    #pragma unroll
    for (int n = 0; n < 4; n++) {
        int gn = base + 4 * tn + n;
        if (gn < NN) {
            float2 al = unpack2(aAL[n]), ah = unpack2(aAH[n]);
            float2 bl = unpack2(aBL[n]), bh = unpack2(aBH[n]);
            A4[gn * 16 + tc] = make_float4(al.x, al.y, ah.x, ah.y);
            B4[gn * 16 + tc] = make_float4(bl.x, bl.y, bh.x, bh.y);
        }
    }
}

// ---------------------------------------------------------------------------
// Kernel 2: edge kernel — tf32 MMA with DIRECT-GLOBAL A-fragments.
// Tile = 64 edges. 8 warps: warp w: eb=w>>1 (16 edges), choff=(w&1)*32.
// Phase A: a-frags loaded straight from gmem (imm offsets off one base ptr),
//          accumulators initialized with b1, 16 MMAs -> C_s (fp32).
// Phase B: h = relu(A[row]+B[col]+C); red.v4 into g_H[col].
// ---------------------------------------------------------------------------
__global__ __launch_bounds__(256)
void edge_kernel(const int* __restrict__ row, const int* __restrict__ col,
                 const float* __restrict__ ea,
                 const float* __restrict__ W1, const float* __restrict__ b1) {
    __shared__ __align__(16) float C_s[TILE_E * CS_STRIDE]; // 17KB
    __shared__ int row_s[TILE_E];
    __shared__ int col_s[TILE_E];

    const int t = threadIdx.x;
    const int w = t >> 5;
    const int lane = t & 31;
    const int lr = lane >> 2;        // fragment groupID (row)
    const int lk = lane & 3;         // fragment threadID-in-group (col)
    const int eb = w >> 1;           // edge block (16 edges)
    const int choff = (w & 1) * 32;  // channel half

    // --- one-time: weight B-fragments (tf32) in registers ---
    const float* Wc = W1 + 128 * 64;               // W1 rows 128..159 = [32k][64c]
    uint32_t wb[4][4][2];                           // [nt][ks][2]
    float bias0[4], bias1[4];
    #pragma unroll
    for (int nt = 0; nt < 4; nt++) {
        int c = choff + 8 * nt + lr;
        #pragma unroll
        for (int ks = 0; ks < 4; ks++) {
            wb[nt][ks][0] = f2tf32(Wc[(8 * ks + lk) * 64 + c]);
            wb[nt][ks][1] = f2tf32(Wc[(8 * ks + lk + 4) * 64 + c]);
        }
        bias0[nt] = b1[choff + 8 * nt + 2 * lk];
        bias1[nt] = b1[choff + 8 * nt + 2 * lk + 1];
    }

    // --- phase-B constants ---
    const int tc = t & 7;            // 8 channels: 8*tc..8*tc+7
    const int teg = t >> 3;          // 0..31 -> edges 2*teg, 2*teg+1
    const float4* A4 = reinterpret_cast<const float4*>(g_A);
    const float4* B4 = reinterpret_cast<const float4*>(g_B);

    for (int tile = blockIdx.x; tile < N_TILES; tile += gridDim.x) {
        const int base = tile * TILE_E;

        __syncthreads();   // previous phase-B done reading C_s / idx
        if (t < TILE_E) { row_s[t] = row[base + t]; col_s[t] = col[base + t]; }

        // ---- phase A: MMA  C = ea @ Wc + b1, A-fragments direct from gmem
        {
            // this thread's fragment base: edge row (base+16*eb+lr), col lk
            const float* p = ea + (size_t)(base + 16 * eb + lr) * EDGE_C + lk;
            float c0[4], c1[4], c2[4], c3[4];
            #pragma unroll
            for (int nt = 0; nt < 4; nt++) {
                c0[nt] = bias0[nt]; c1[nt] = bias1[nt];
                c2[nt] = bias0[nt]; c3[nt] = bias1[nt];
            }
            #pragma unroll
            for (int ks = 0; ks < 4; ks++) {
                // rows lr / lr+8 (offset 8*EDGE_C floats), cols 8ks+lk / +4
                uint32_t a0 = f2tf32(p[8 * ks]);
                uint32_t a1 = f2tf32(p[8 * EDGE_C + 8 * ks]);
                uint32_t a2 = f2tf32(p[8 * ks + 4]);
                uint32_t a3 = f2tf32(p[8 * EDGE_C + 8 * ks + 4]);
                #pragma unroll
                for (int nt = 0; nt < 4; nt++)
                    mma_tf32(c0[nt], c1[nt], c2[nt], c3[nt],
                             a0, a1, a2, a3, wb[nt][ks][0], wb[nt][ks][1]);
            }
            // store C fragments to C_s
            #pragma unroll
            for (int nt = 0; nt < 4; nt++) {
                int ccol = choff + 8 * nt + 2 * lk;
                float2* p0 = reinterpret_cast<float2*>(C_s + (16 * eb + lr) * CS_STRIDE + ccol);
                float2* p1 = reinterpret_cast<float2*>(C_s + (16 * eb + lr + 8) * CS_STRIDE + ccol);
                *p0 = make_float2(c0[nt], c1[nt]);
                *p1 = make_float2(c2[nt], c3[nt]);
            }
        }
        __syncthreads();

        // ---- phase B: gather + add + relu + scatter ----
        #pragma unroll
        for (int e2 = 0; e2 < 2; e2++) {
            const int e = 2 * teg + e2;
            const int r = row_s[e], c = col_s[e];
            float4 a0 = A4[r * 16 + 2 * tc], a1 = A4[r * 16 + 2 * tc + 1];
            float4 g0 = B4[c * 16 + 2 * tc], g1 = B4[c * 16 + 2 * tc + 1];
            float4 m0 = *reinterpret_cast<float4*>(C_s + e * CS_STRIDE + 8 * tc);
            float4 m1 = *reinterpret_cast<float4*>(C_s + e * CS_STRIDE + 8 * tc + 4);
            float4 h0 = make_float4(
                fmaxf(a0.x + g0.x + m0.x, 0.f),
                fmaxf(a0.y + g0.y + m0.y, 0.f),
                fmaxf(a0.z + g0.z + m0.z, 0.f),
                fmaxf(a0.w + g0.w + m0.w, 0.f));
            float4 h1 = make_float4(
                fmaxf(a1.x + g1.x + m1.x, 0.f),
                fmaxf(a1.y + g1.y + m1.y, 0.f),
                fmaxf(a1.z + g1.z + m1.z, 0.f),
                fmaxf(a1.w + g1.w + m1.w, 0.f));
            red_add_v4(g_H + (size_t)c * OUT_C + 8 * tc, h0);
            red_add_v4(g_H + (size_t)c * OUT_C + 8 * tc + 4, h1);
        }
    }
}

// ---------------------------------------------------------------------------
// Kernel 3: node GEMM + mean + bias:  out = (H @ W2) / max(deg,1) + b2
// ---------------------------------------------------------------------------
__global__ __launch_bounds__(256)
void out_kernel(const float* __restrict__ W2, const float* __restrict__ b2,
                float* __restrict__ out) {
    __shared__ __align__(16) float W2_s[OUT_C * OUT_C];
    __shared__ __align__(16) float h_s[64 * OUT_C];

    const int t = threadIdx.x;
    for (int i = t; i < OUT_C * OUT_C; i += 256) W2_s[i] = W2[i];

    const int tc = t & 15;
    const int tn = t >> 4;
    const int base = blockIdx.x * 64;
    {
        const float4* H4 = reinterpret_cast<const float4*>(g_H);
        float4* hs4 = reinterpret_cast<float4*>(h_s);
        #pragma unroll
        for (int i = 0; i < 4; i++) {
            int id = t + 256 * i;
            int n = id >> 4, q = id & 15;
            int gn = base + n;
            float4 v = make_float4(0.f, 0.f, 0.f, 0.f);
            if (gn < NN) v = H4[gn * 16 + q];
            hs4[n * 16 + q] = v;
        }
    }
    __syncthreads();

    u64 aL[4], aH[4];
    #pragma unroll
    for (int n = 0; n < 4; n++) { aL[n] = 0; aH[n] = 0; }

    const ulonglong2* w2 = reinterpret_cast<const ulonglong2*>(W2_s);
    const float4* hs4 = reinterpret_cast<const float4*>(h_s);

    #pragma unroll
    for (int kb = 0; kb < OUT_C / 4; kb++) {
        ulonglong2 w[4];
        #pragma unroll
        for (int kk = 0; kk < 4; kk++) w[kk] = w2[(4 * kb + kk) * 16 + tc];
        #pragma unroll
        for (int n = 0; n < 4; n++) {
            float4 v4 = hs4[(4 * tn + n) * 16 + kb];
            u64 d0 = dup2(v4.x), d1 = dup2(v4.y), d2 = dup2(v4.z), d3 = dup2(v4.w);
            fma2(aL[n], d0, w[0].x); fma2(aH[n], d0, w[0].y);
            fma2(aL[n], d1, w[1].x); fma2(aH[n], d1, w[1].y);
            fma2(aL[n], d2, w[2].x); fma2(aH[n], d2, w[2].y);
            fma2(aL[n], d3, w[3].x); fma2(aH[n], d3, w[3].y);
        }
    }

    const float4 b2v = *reinterpret_cast<const float4*>(b2 + 4 * tc);
    float4* out4 = reinterpret_cast<float4*>(out);
    #pragma unroll
    for (int n = 0; n < 4; n++) {
        int gn = base + 4 * tn + n;
        if (gn < NN) {
            int d = g_deg[gn];
            float2 lo = unpack2(aL[n]), hi = unpack2(aH[n]);
            float4 o;
            if (d == 0) {
                o = make_float4(0.f, 0.f, 0.f, 0.f);
            } else {
                float inv = 1.0f / (float)d;
                o = make_float4(lo.x * inv + b2v.x, lo.y * inv + b2v.y,
                                hi.x * inv + b2v.z, hi.y * inv + b2v.w);
            }
            out4[gn * 16 + tc] = o;
        }
    }
}

// ---------------------------------------------------------------------------
// Launch
// ---------------------------------------------------------------------------
extern "C" void kernel_launch(void* const* d_in, const int* in_sizes, int n_in,
                              void* d_out, int out_size) {
    const float* x    = (const float*)d_in[0];
    const int*   eidx = (const int*)d_in[1];     // [2][E]: row then col
    const float* ea   = (const float*)d_in[2];
    const float* W1   = (const float*)d_in[3];
    const float* b1   = (const float*)d_in[4];
    const float* W2   = (const float*)d_in[5];
    const float* b2   = (const float*)d_in[6];
    float* out = (float*)d_out;

    const int* row = eidx;
    const int* col = eidx + EE;

    // 0) zero H + degrees
    {
        int total = (NN * OUT_C) / 4;
        zero_kernel<<<(total + 255) / 256, 256>>>();
    }
    // 0b) degree histogram
    hist_kernel<<<(EE + 255) / 256, 256>>>(col);
    // 1) per-node projections A, B
    pre_kernel<<<(NN + 63) / 64, 256>>>(x, W1);
    // 2) edge: tensor-core layer-1 (direct-gmem fragments) + scatter h
    edge_kernel<<<1184, 256>>>(row, col, ea, W1, b1);
    // 3) node GEMM + mean + bias
    out_kernel<<<(NN + 63) / 64, 256>>>(W2, b2, out);
}